// round 1
// baseline (speedup 1.0000x reference)
#include <cuda_runtime.h>

#define H_  256
#define B_  8
#define L_  4096
#define DD_ 32
#define LC  64
#define NCH 64
#define BH  (B_*H_)

// Scratch (static __device__ globals -- no allocation allowed)
__device__ __align__(16) float  g_A [H_][128][64];   // per-head GEMM-Y matrix, k-major [k][i]
__device__ __align__(16) float  g_E1[H_][64][64];    // per-head GEMM-P matrix, k-major [m][dt]
__device__ __align__(16) float2 g_c0[H_][DD_];       // initial carries (g/r)
__device__ __align__(16) float2 g_rL[H_][DD_];       // r^LC
__device__ __align__(16) float  g_P [BH][NCH][64];   // w*P per chunk (interleaved re/im)
__device__ __align__(16) float  g_C [BH][NCH][64];   // carries per chunk (interleaved re/im)

// ---------------------------------------------------------------------------
// Kernel 0: per-head setup. Builds r powers, w, g, c0, r^LC, E1' (w folded),
// filter f[0..LC), and the combined A matrix (injection + Toeplitz + D).
// ---------------------------------------------------------------------------
__global__ void k_setup(const float* __restrict__ theta,
                        const float* __restrict__ a,
                        const float* __restrict__ Dp,
                        const float* __restrict__ b_p,
                        const float* __restrict__ c_p,
                        const float* __restrict__ x0) {
    int h = blockIdx.x;
    int t = threadIdx.x;              // 64 threads
    __shared__ float2 rp[LC + 1][DD_];
    __shared__ float2 sw[DD_];
    __shared__ float  sf[LC];
    const float T = 1.0f / (float)(L_ - 1);

    if (t < DD_) {
        int d   = t;
        int idx = h * DD_ + d;
        float av = fabsf(a[idx]);
        float th = theta[idx];
        // r = exp(ls*T), ls = -av + i*th
        float er = expf(-av * T);
        float rr = er * cosf(th * T);
        float ri = er * sinf(th * T);
        // term0 = (r - 1) / ls
        float lr = -av, li = th;
        float den = lr * lr + li * li;
        float nr = rr - 1.0f, ni = ri;
        float t0r = (nr * lr + ni * li) / den;
        float t0i = (ni * lr - nr * li) / den;
        // w = 2 * term0 * (b_p * c_p)
        float q  = b_p[idx] * c_p[idx];
        float wr = 2.0f * t0r * q;
        float wi = 2.0f * t0i * q;
        sw[d] = make_float2(wr, wi);
        // init coefficient g = 4*T*c_p*x0 ; c0 = g / r
        float g   = 4.0f * T * c_p[idx] * x0[idx];
        float rm2 = rr * rr + ri * ri;
        g_c0[h][d] = make_float2(g * rr / rm2, -g * ri / rm2);
        // powers r^0 .. r^LC
        float pr = 1.0f, pi = 0.0f;
        for (int p = 0; p <= LC; p++) {
            rp[p][d] = make_float2(pr, pi);
            float npr = pr * rr - pi * ri;
            float npi = pr * ri + pi * rr;
            pr = npr; pi = npi;
        }
        g_rL[h][d] = rp[LC][d];
        // E1'[m][2d],[2d+1] = (w * r^{LC-1-m}).re/.im  (w folded into P)
        for (int m = 0; m < LC; m++) {
            float2 rw = rp[LC - 1 - m][d];
            g_E1[h][m][2 * d]     = wr * rw.x - wi * rw.y;
            g_E1[h][m][2 * d + 1] = wr * rw.y + wi * rw.x;
        }
    }
    __syncthreads();

    // filter f[j] = Re sum_d w_d r_d^j
    {
        int j = t;
        float s = 0.0f;
        #pragma unroll
        for (int d = 0; d < DD_; d++) {
            float2 w = sw[d], p = rp[j][d];
            s += w.x * p.x - w.y * p.y;
        }
        sf[j] = s;
    }
    __syncthreads();

    // A matrix: k<64 -> injection columns (Re r^{i+1}, -Im r^{i+1});
    //           k>=64 -> Toeplitz f[i-m] (+ D on diagonal)
    float Dv = Dp[h];
    int i = t;
    for (int k = 0; k < LC; k++) {
        int d = k >> 1;
        float2 r1 = rp[i + 1][d];
        g_A[h][k][i] = (k & 1) ? -r1.y : r1.x;
    }
    for (int m = 0; m < LC; m++) {
        float v = 0.0f;
        if (i > m)       v = sf[i - m];
        else if (i == m) v = sf[0] + Dv;
        g_A[h][LC + m][i] = v;
    }
}

// ---------------------------------------------------------------------------
// Kernel 1: per-(b,h) GEMM  wP[dt][ch] = E1'[m][dt] * u[m][ch]   (K = 64)
// ---------------------------------------------------------------------------
__global__ __launch_bounds__(256) void k_P(const float* __restrict__ u) {
    int bh = blockIdx.x;
    int h  = bh & (H_ - 1);
    int tid = threadIdx.x;
    __shared__ __align__(16) float As[64][64];
    __shared__ __align__(16) float Bs[64][68];

    // load E1 (k-major) straight
    {
        const float4* src = (const float4*)&g_E1[h][0][0];
        float4* dst = (float4*)&As[0][0];
        for (int i = tid; i < 1024; i += 256) dst[i] = src[i];
    }
    // load u chunk-transposed: Bs[m][ch]
    {
        const float* ub = u + (size_t)bh * L_;
        for (int i = tid * 4; i < L_; i += 1024) {
            float4 v = *(const float4*)(ub + i);
            int ch = i >> 6, m = i & 63;
            Bs[m][ch] = v.x; Bs[m + 1][ch] = v.y;
            Bs[m + 2][ch] = v.z; Bs[m + 3][ch] = v.w;
        }
    }
    __syncthreads();

    int ti = tid & 15, tc = tid >> 4;
    float acc[4][4];
    #pragma unroll
    for (int cc = 0; cc < 4; cc++)
        #pragma unroll
        for (int ii = 0; ii < 4; ii++) acc[cc][ii] = 0.0f;

    #pragma unroll 8
    for (int k = 0; k < 64; k++) {
        float4 a4 = *(const float4*)&As[k][ti * 4];
        float4 b4 = *(const float4*)&Bs[k][tc * 4];
        float av[4] = {a4.x, a4.y, a4.z, a4.w};
        float bv[4] = {b4.x, b4.y, b4.z, b4.w};
        #pragma unroll
        for (int cc = 0; cc < 4; cc++)
            #pragma unroll
            for (int ii = 0; ii < 4; ii++)
                acc[cc][ii] = fmaf(av[ii], bv[cc], acc[cc][ii]);
    }

    #pragma unroll
    for (int cc = 0; cc < 4; cc++) {
        int ch = tc * 4 + cc;
        float4 o = make_float4(acc[cc][0], acc[cc][1], acc[cc][2], acc[cc][3]);
        *(float4*)&g_P[bh][ch][ti * 4] = o;
    }
}

// ---------------------------------------------------------------------------
// Kernel 2: carry scan across chunks.  c_{j+1} = r^LC * c_j + wP_j
// One thread per (b,h,d): 65536 threads, 64 sequential steps.
// ---------------------------------------------------------------------------
__global__ void k_scan() {
    int gid = blockIdx.x * blockDim.x + threadIdx.x;
    int d  = gid & (DD_ - 1);
    int bh = gid >> 5;
    int h  = bh & (H_ - 1);
    float2 c  = g_c0[h][d];
    float2 rl = g_rL[h][d];
    float2* Pp = (float2*)&g_P[bh][0][0];
    float2* Cp = (float2*)&g_C[bh][0][0];
    #pragma unroll 4
    for (int j = 0; j < NCH; j++) {
        Cp[j * DD_ + d] = c;
        float2 p = Pp[j * DD_ + d];
        float cr = rl.x * c.x - rl.y * c.y + p.x;
        float ci = rl.x * c.y + rl.y * c.x + p.y;
        c = make_float2(cr, ci);
    }
}

// ---------------------------------------------------------------------------
// Kernel 3: per-(b,h) output GEMM (K = 128 in two K=64 stages):
//   y[i][ch] = A[0:64][i] . C[ch][:]  +  A[64:128][i] . u[ch*64 + :]
// ---------------------------------------------------------------------------
__global__ __launch_bounds__(256) void k_Y(const float* __restrict__ u,
                                           float* __restrict__ out) {
    int bh = blockIdx.x;
    int h  = bh & (H_ - 1);
    int tid = threadIdx.x;
    int ti = tid & 15, tc = tid >> 4;
    __shared__ __align__(16) float As[64][64];
    __shared__ __align__(16) float Bs[64][68];

    float acc[4][4];
    #pragma unroll
    for (int cc = 0; cc < 4; cc++)
        #pragma unroll
        for (int ii = 0; ii < 4; ii++) acc[cc][ii] = 0.0f;

    #pragma unroll 1
    for (int stage = 0; stage < 2; stage++) {
        // A rows [stage*64 .. stage*64+63]
        {
            const float4* src = (const float4*)&g_A[h][stage * 64][0];
            float4* dst = (float4*)&As[0][0];
            for (int i = tid; i < 1024; i += 256) dst[i] = src[i];
        }
        // B rows: stage 0 -> carries (transposed), stage 1 -> u (transposed)
        {
            const float* src = (stage == 0) ? &g_C[bh][0][0]
                                            : (u + (size_t)bh * L_);
            for (int i = tid * 4; i < 4096; i += 1024) {
                float4 v = *(const float4*)(src + i);
                int ch = i >> 6, k = i & 63;
                Bs[k][ch] = v.x; Bs[k + 1][ch] = v.y;
                Bs[k + 2][ch] = v.z; Bs[k + 3][ch] = v.w;
            }
        }
        __syncthreads();

        #pragma unroll 8
        for (int k = 0; k < 64; k++) {
            float4 a4 = *(const float4*)&As[k][ti * 4];
            float4 b4 = *(const float4*)&Bs[k][tc * 4];
            float av[4] = {a4.x, a4.y, a4.z, a4.w};
            float bv[4] = {b4.x, b4.y, b4.z, b4.w};
            #pragma unroll
            for (int cc = 0; cc < 4; cc++)
                #pragma unroll
                for (int ii = 0; ii < 4; ii++)
                    acc[cc][ii] = fmaf(av[ii], bv[cc], acc[cc][ii]);
        }
        __syncthreads();
    }

    float* ob = out + (size_t)bh * L_;
    #pragma unroll
    for (int cc = 0; cc < 4; cc++) {
        int ch = tc * 4 + cc;
        float4 o = make_float4(acc[cc][0], acc[cc][1], acc[cc][2], acc[cc][3]);
        *(float4*)(ob + ch * 64 + ti * 4) = o;
    }
}

// ---------------------------------------------------------------------------
extern "C" void kernel_launch(void* const* d_in, const int* in_sizes, int n_in,
                              void* d_out, int out_size) {
    const float* u     = (const float*)d_in[0];
    const float* theta = (const float*)d_in[1];
    const float* a     = (const float*)d_in[2];
    const float* Dp    = (const float*)d_in[3];
    const float* b_p   = (const float*)d_in[4];
    const float* c_p   = (const float*)d_in[5];
    const float* x0    = (const float*)d_in[6];
    float* out = (float*)d_out;

    k_setup<<<H_, 64>>>(theta, a, Dp, b_p, c_p, x0);
    k_P<<<BH, 256>>>(u);
    k_scan<<<BH * DD_ / 256, 256>>>();
    k_Y<<<BH, 256>>>(u, out);
}

// round 3
// speedup vs baseline: 2.2627x; 2.2627x over previous
#include <cuda_runtime.h>
#include <cstdint>

#define NH 256
#define NB 8
#define NL 4096

// ---- static device scratch (no allocation allowed) ----
__device__ float  g_YB [NH * 64 * 128];  // per-head Y B-operand [i][k], k-permuted, tf32-rounded
__device__ float  g_E1b[NH * 64 * 64];   // per-head P B-operand [dt][m], m-permuted, tf32-rounded
__device__ float2 g_c0[NH][32];
__device__ float2 g_rL[NH][32];

static __device__ __forceinline__ uint32_t f2tf(float f) {
    uint32_t u;
    asm("cvt.rna.tf32.f32 %0, %1;" : "=r"(u) : "f"(f));
    return u;
}
// permute k within each 8-group so B fragment (k, k+4) is one contiguous float2
static __device__ __forceinline__ int kperm(int k) {
    return (k & ~7) | ((k & 3) << 1) | ((k >> 2) & 1);
}
static __device__ __forceinline__ void mma8(float* c, uint32_t a0, uint32_t a1,
                                            uint32_t a2, uint32_t a3,
                                            uint32_t b0, uint32_t b1) {
    asm volatile(
        "mma.sync.aligned.m16n8k8.row.col.f32.tf32.tf32.f32 "
        "{%0,%1,%2,%3},{%4,%5,%6,%7},{%8,%9},{%0,%1,%2,%3};"
        : "+f"(c[0]), "+f"(c[1]), "+f"(c[2]), "+f"(c[3])
        : "r"(a0), "r"(a1), "r"(a2), "r"(a3), "r"(b0), "r"(b1));
}

// ---------------------------------------------------------------------------
// Setup: per-head basis -> B-operand matrices (tf32-rounded, k-permuted) + scan consts
// ---------------------------------------------------------------------------
__global__ __launch_bounds__(64) void k_setup(const float* __restrict__ theta,
                                              const float* __restrict__ a,
                                              const float* __restrict__ b_p,
                                              const float* __restrict__ c_p,
                                              const float* __restrict__ x0) {
    __shared__ float2 rp[65][32];
    __shared__ float2 sw[32];
    __shared__ float  sf[64];
    int h = blockIdx.x, t = threadIdx.x;
    const float T = 1.0f / (float)(NL - 1);

    if (t < 32) {
        int d = t, idx = h * 32 + d;
        float av = fabsf(a[idx]);
        float th = theta[idx];
        float er = expf(-av * T);
        float rr = er * cosf(th * T), ri = er * sinf(th * T);
        float lr = -av, li = th;
        float den = lr * lr + li * li;
        float nr = rr - 1.0f, ni = ri;
        float t0r = (nr * lr + ni * li) / den;
        float t0i = (ni * lr - nr * li) / den;
        float q = b_p[idx] * c_p[idx];
        sw[d] = make_float2(2.0f * t0r * q, 2.0f * t0i * q);
        float g = 4.0f * T * c_p[idx] * x0[idx];
        float rm2 = rr * rr + ri * ri;
        g_c0[h][d] = make_float2(g * rr / rm2, -g * ri / rm2);
        float pr = 1.0f, pi = 0.0f;
        for (int p = 0; p <= 64; p++) {
            rp[p][d] = make_float2(pr, pi);
            float npr = pr * rr - pi * ri;
            float npi = pr * ri + pi * rr;
            pr = npr; pi = npi;
        }
        g_rL[h][d] = rp[64][d];
    }
    __syncthreads();
    {   // filter f[j] = Re sum_d w_d r_d^j
        float s = 0.0f;
        #pragma unroll
        for (int d = 0; d < 32; d++) {
            float2 w = sw[d], p = rp[t][d];
            s += w.x * p.x - w.y * p.y;
        }
        sf[t] = s;
    }
    __syncthreads();
    // E1b[dt][m] = Re/Im( w_d * r_d^{63-m} ), d = dt>>1; stored m-permuted, tf32-rounded
    for (int e = t; e < 4096; e += 64) {
        int dt = e >> 6, m = e & 63, d = dt >> 1;
        float2 w = sw[d], rv = rp[63 - m][d];
        float v = (dt & 1) ? (w.x * rv.y + w.y * rv.x) : (w.x * rv.x - w.y * rv.y);
        g_E1b[h * 4096 + dt * 64 + kperm(m)] = __uint_as_float(f2tf(v));
    }
    // YB[i][k]: k<64 injection (Re r^{i+1} / -Im r^{i+1}); k>=64 Toeplitz f (D excluded)
    for (int e = t; e < 8192; e += 64) {
        int i = e >> 7, k = e & 127;
        float v;
        if (k < 64) {
            float2 r1 = rp[i + 1][k >> 1];
            v = (k & 1) ? -r1.y : r1.x;
        } else {
            int m = k - 64;
            v = (i > m) ? sf[i - m] : ((i == m) ? sf[0] : 0.0f);
        }
        g_YB[h * 8192 + i * 128 + kperm(k)] = __uint_as_float(f2tf(v));
    }
}

// ---------------------------------------------------------------------------
// Fused kernel: one CTA = (h, b-pair). P mma -> scan -> Y mma -> D*u epilogue
// SMEM (floats): Us[128][68] @0, CPs[128][68] @8704, E1s[64][68] @17408, YBs[64][132] @21760
// ---------------------------------------------------------------------------
#define P_US  0
#define P_CP  8704
#define P_E1  17408
#define P_YB  21760
#define SMEMF (30208 * 4)

__global__ __launch_bounds__(256, 1) void k_fused(const float* __restrict__ u,
                                                  const float* __restrict__ Dp,
                                                  float* __restrict__ out) {
    extern __shared__ float sm[];
    float* Us  = sm + P_US;   // pitch 68
    float* CPs = sm + P_CP;   // pitch 68
    float* E1s = sm + P_E1;   // pitch 68
    float* YBs = sm + P_YB;   // pitch 132

    int tid  = threadIdx.x;
    int lane = tid & 31, warp = tid >> 5;
    int h = blockIdx.x >> 2, b0 = (blockIdx.x & 3) * 2;

    // ---- loads ----
    {   // u: 128 rows x 64 floats (row = bl*64 + ch)
        #pragma unroll
        for (int it = 0; it < 8; it++) {
            int idx = it * 256 + tid;        // 2048 float4
            int row = idx >> 4, c4 = (idx & 15) << 2;
            const float* src = u + ((size_t)((b0 + (row >> 6)) * NH + h)) * NL
                                 + (row & 63) * 64 + c4;
            float4 v = *(const float4*)src;
            *(float4*)&Us[row * 68 + c4] = v;
        }
        const float4* gE = (const float4*)&g_E1b[h * 4096];
        #pragma unroll
        for (int it = 0; it < 4; it++) {
            int idx = it * 256 + tid;        // 1024 float4
            int row = idx >> 4, c4 = (idx & 15) << 2;
            *(float4*)&E1s[row * 68 + c4] = gE[idx];
        }
        const float4* gY = (const float4*)&g_YB[h * 8192];
        #pragma unroll
        for (int it = 0; it < 8; it++) {
            int idx = it * 256 + tid;        // 2048 float4
            int row = idx >> 5, c4 = (idx & 31) << 2;
            *(float4*)&YBs[row * 132 + c4] = gY[idx];
        }
    }
    __syncthreads();

    int m0 = warp * 16;
    int ar = m0 + (lane >> 2);   // A rows: ar, ar+8
    int ac = lane & 3;
    int bn = lane >> 2;          // B n within tile
    int bk2 = (lane & 3) * 2;    // permuted B k offset (float2)

    // ---- P GEMM: P[row][dt] = sum_m U[row][m] * E1[dt][m]  (K=64) ----
    float pc[8][4];
    #pragma unroll
    for (int j = 0; j < 8; j++)
        #pragma unroll
        for (int q = 0; q < 4; q++) pc[j][q] = 0.0f;

    #pragma unroll
    for (int ks = 0; ks < 8; ks++) {
        int k0 = ks * 8;
        uint32_t a0 = f2tf(Us[ar * 68 + k0 + ac]);
        uint32_t a1 = f2tf(Us[(ar + 8) * 68 + k0 + ac]);
        uint32_t a2 = f2tf(Us[ar * 68 + k0 + ac + 4]);
        uint32_t a3 = f2tf(Us[(ar + 8) * 68 + k0 + ac + 4]);
        #pragma unroll
        for (int j = 0; j < 8; j++) {
            float2 bv = *(float2*)&E1s[(j * 8 + bn) * 68 + k0 + bk2];
            mma8(pc[j], a0, a1, a2, a3, __float_as_uint(bv.x), __float_as_uint(bv.y));
        }
    }
    // write P into CPs (natural dt order)
    {
        int ra = m0 + (lane >> 2);
        #pragma unroll
        for (int j = 0; j < 8; j++) {
            int col = j * 8 + 2 * (lane & 3);
            *(float2*)&CPs[ra * 68 + col]       = make_float2(pc[j][0], pc[j][1]);
            *(float2*)&CPs[(ra + 8) * 68 + col] = make_float2(pc[j][2], pc[j][3]);
        }
    }
    __syncthreads();

    // ---- carry scan (in place): c_{j+1} = r^64 * c_j + P_j ----
    if (tid < 64) {
        int bl = tid >> 5, d = tid & 31;
        float2 c  = g_c0[h][d];
        float2 rl = g_rL[h][d];
        float* basep = &CPs[(bl * 64) * 68 + 2 * d];
        #pragma unroll 4
        for (int ch = 0; ch < 64; ch++) {
            float2 p = *(float2*)(basep + ch * 68);
            *(float2*)(basep + ch * 68) = c;
            float cr = fmaf(rl.x, c.x, fmaf(-rl.y, c.y, p.x));
            float ci = fmaf(rl.x, c.y, fmaf( rl.y, c.x, p.y));
            c = make_float2(cr, ci);
        }
    }
    __syncthreads();

    // ---- Y GEMM: y[row][i] = sum_dt C[row][dt]*YB[i][dt] + sum_m U[row][m]*YB[i][64+m] ----
    float yc[8][4];
    #pragma unroll
    for (int j = 0; j < 8; j++)
        #pragma unroll
        for (int q = 0; q < 4; q++) yc[j][q] = 0.0f;

    #pragma unroll
    for (int ks = 0; ks < 8; ks++) {      // K half 1: carries
        int k0 = ks * 8;
        uint32_t a0 = f2tf(CPs[ar * 68 + k0 + ac]);
        uint32_t a1 = f2tf(CPs[(ar + 8) * 68 + k0 + ac]);
        uint32_t a2 = f2tf(CPs[ar * 68 + k0 + ac + 4]);
        uint32_t a3 = f2tf(CPs[(ar + 8) * 68 + k0 + ac + 4]);
        #pragma unroll
        for (int j = 0; j < 8; j++) {
            float2 bv = *(float2*)&YBs[(j * 8 + bn) * 132 + k0 + bk2];
            mma8(yc[j], a0, a1, a2, a3, __float_as_uint(bv.x), __float_as_uint(bv.y));
        }
    }
    #pragma unroll
    for (int ks = 0; ks < 8; ks++) {      // K half 2: u (Toeplitz)
        int k0 = ks * 8;
        uint32_t a0 = f2tf(Us[ar * 68 + k0 + ac]);
        uint32_t a1 = f2tf(Us[(ar + 8) * 68 + k0 + ac]);
        uint32_t a2 = f2tf(Us[ar * 68 + k0 + ac + 4]);
        uint32_t a3 = f2tf(Us[(ar + 8) * 68 + k0 + ac + 4]);
        #pragma unroll
        for (int j = 0; j < 8; j++) {
            float2 bv = *(float2*)&YBs[(j * 8 + bn) * 132 + 64 + k0 + bk2];
            mma8(yc[j], a0, a1, a2, a3, __float_as_uint(bv.x), __float_as_uint(bv.y));
        }
    }

    // ---- epilogue: y = Y + D*u (exact fp32), straight from accumulators ----
    {
        float Dv = __ldg(&Dp[h]);
        int ra = m0 + (lane >> 2);
        #pragma unroll
        for (int half = 0; half < 2; half++) {
            int r = ra + half * 8;
            float* op = out + ((size_t)((b0 + (r >> 6)) * NH + h)) * NL + (r & 63) * 64;
            #pragma unroll
            for (int j = 0; j < 8; j++) {
                int col = j * 8 + 2 * (lane & 3);
                float2 uv = *(float2*)&Us[r * 68 + col];
                float2 o2;
                o2.x = fmaf(Dv, uv.x, yc[j][half * 2 + 0]);
                o2.y = fmaf(Dv, uv.y, yc[j][half * 2 + 1]);
                *(float2*)(op + col) = o2;
            }
        }
    }
}

// ---------------------------------------------------------------------------
extern "C" void kernel_launch(void* const* d_in, const int* in_sizes, int n_in,
                              void* d_out, int out_size) {
    (void)in_sizes; (void)n_in; (void)out_size;
    const float* u     = (const float*)d_in[0];
    const float* theta = (const float*)d_in[1];
    const float* a     = (const float*)d_in[2];
    const float* Dp    = (const float*)d_in[3];
    const float* b_p   = (const float*)d_in[4];
    const float* c_p   = (const float*)d_in[5];
    const float* x0    = (const float*)d_in[6];
    float* out = (float*)d_out;

    cudaFuncSetAttribute(k_fused, cudaFuncAttributeMaxDynamicSharedMemorySize, SMEMF);

    k_setup<<<NH, 64>>>(theta, a, b_p, c_p, x0);
    k_fused<<<1024, 256, SMEMF>>>(u, Dp, out);
}

// round 4
// speedup vs baseline: 2.5047x; 1.1070x over previous
#include <cuda_runtime.h>
#include <cstdint>

#define NH 256
#define NB 8
#define NL 4096

// ---- static device scratch (no allocation allowed) ----
__device__ float  g_YB [NH * 64 * 128];  // per-head Y B-operand [i][k], k-permuted, tf32-rounded
__device__ float  g_E1b[NH * 64 * 64];   // per-head P B-operand [dt][m], m-permuted, tf32-rounded
__device__ float2 g_c0[NH][32];
__device__ float2 g_rL[NH][32];

static __device__ __forceinline__ uint32_t f2tf(float f) {
    uint32_t u;
    asm("cvt.rna.tf32.f32 %0, %1;" : "=r"(u) : "f"(f));
    return u;
}
// permute k within each 8-group so B fragment (k, k+4) is one contiguous float2
static __device__ __forceinline__ int kperm(int k) {
    return (k & ~7) | ((k & 3) << 1) | ((k >> 2) & 1);
}
static __device__ __forceinline__ void mma8(float* c, uint32_t a0, uint32_t a1,
                                            uint32_t a2, uint32_t a3,
                                            uint32_t b0, uint32_t b1) {
    asm volatile(
        "mma.sync.aligned.m16n8k8.row.col.f32.tf32.tf32.f32 "
        "{%0,%1,%2,%3},{%4,%5,%6,%7},{%8,%9},{%0,%1,%2,%3};"
        : "+f"(c[0]), "+f"(c[1]), "+f"(c[2]), "+f"(c[3])
        : "r"(a0), "r"(a1), "r"(a2), "r"(a3), "r"(b0), "r"(b1));
}
static __device__ __forceinline__ uint32_t s2u(const void* p) {
    uint32_t a;
    asm("{ .reg .u64 t; cvta.to.shared.u64 t, %1; cvt.u32.u64 %0, t; }" : "=r"(a) : "l"(p));
    return a;
}
static __device__ __forceinline__ void cpa16(uint32_t dst, const void* src) {
    asm volatile("cp.async.cg.shared.global [%0], [%1], 16;" :: "r"(dst), "l"(src) : "memory");
}

// ---------------------------------------------------------------------------
// Setup: per-head basis -> B-operand matrices (tf32-rounded, k-permuted) + scan consts
// ---------------------------------------------------------------------------
__global__ __launch_bounds__(128) void k_setup(const float* __restrict__ theta,
                                               const float* __restrict__ a,
                                               const float* __restrict__ b_p,
                                               const float* __restrict__ c_p,
                                               const float* __restrict__ x0) {
    __shared__ float2 rp[65][32];
    __shared__ float2 sw[32];
    __shared__ float  sf[64];
    int h = blockIdx.x, t = threadIdx.x;
    const float T = 1.0f / (float)(NL - 1);

    if (t < 32) {
        int d = t, idx = h * 32 + d;
        float av = fabsf(a[idx]);
        float th = theta[idx];
        float er = expf(-av * T);
        float rr = er * cosf(th * T), ri = er * sinf(th * T);
        float lr = -av, li = th;
        float den = lr * lr + li * li;
        float nr = rr - 1.0f, ni = ri;
        float t0r = (nr * lr + ni * li) / den;
        float t0i = (ni * lr - nr * li) / den;
        float q = b_p[idx] * c_p[idx];
        sw[d] = make_float2(2.0f * t0r * q, 2.0f * t0i * q);
        float g = 4.0f * T * c_p[idx] * x0[idx];
        float rm2 = rr * rr + ri * ri;
        g_c0[h][d] = make_float2(g * rr / rm2, -g * ri / rm2);
        float pr = 1.0f, pi = 0.0f;
        for (int p = 0; p <= 64; p++) {
            rp[p][d] = make_float2(pr, pi);
            float npr = pr * rr - pi * ri;
            float npi = pr * ri + pi * rr;
            pr = npr; pi = npi;
        }
        g_rL[h][d] = rp[64][d];
    }
    __syncthreads();
    if (t < 64) {   // filter f[j] = Re sum_d w_d r_d^j
        float s = 0.0f;
        #pragma unroll
        for (int d = 0; d < 32; d++) {
            float2 w = sw[d], p = rp[t][d];
            s += w.x * p.x - w.y * p.y;
        }
        sf[t] = s;
    }
    __syncthreads();
    // E1b[dt][m] = Re/Im( w_d * r_d^{63-m} ), d = dt>>1; stored m-permuted, tf32-rounded
    for (int e = t; e < 4096; e += 128) {
        int dt = e >> 6, m = e & 63, d = dt >> 1;
        float2 w = sw[d], rv = rp[63 - m][d];
        float v = (dt & 1) ? (w.x * rv.y + w.y * rv.x) : (w.x * rv.x - w.y * rv.y);
        g_E1b[h * 4096 + dt * 64 + kperm(m)] = __uint_as_float(f2tf(v));
    }
    // YB[i][k]: k<64 injection (Re r^{i+1} / -Im r^{i+1}); k>=64 Toeplitz f (D excluded)
    for (int e = t; e < 8192; e += 128) {
        int i = e >> 7, k = e & 127;
        float v;
        if (k < 64) {
            float2 r1 = rp[i + 1][k >> 1];
            v = (k & 1) ? -r1.y : r1.x;
        } else {
            int m = k - 64;
            v = (i > m) ? sf[i - m] : ((i == m) ? sf[0] : 0.0f);
        }
        g_YB[h * 8192 + i * 128 + kperm(k)] = __uint_as_float(f2tf(v));
    }
}

// ---------------------------------------------------------------------------
// Fused kernel: one CTA = (h, b-pair). P mma -> scan -> Y mma -> D*u epilogue
// SMEM (floats): Us[128][68] @0, YBs[64][132] @8704,
//                CE @17152: first acts as E1s[64][68], then reused as CPs[128][68]
// ---------------------------------------------------------------------------
#define P_US  0
#define P_YB  8704
#define P_CE  17152
#define NFLT  25856
#define SMEMF (NFLT * 4)

__global__ __launch_bounds__(256, 2) void k_fused(const float* __restrict__ u,
                                                  const float* __restrict__ Dp,
                                                  float* __restrict__ out) {
    extern __shared__ float sm[];
    float* Us  = sm + P_US;   // pitch 68
    float* YBs = sm + P_YB;   // pitch 132
    float* E1s = sm + P_CE;   // pitch 68 (phase 1)
    float* CPs = sm + P_CE;   // pitch 68 (phase 2+)

    int tid  = threadIdx.x;
    int lane = tid & 31, warp = tid >> 5;
    int h = blockIdx.x >> 2, b0 = (blockIdx.x & 3) * 2;
    float Dv = __ldg(&Dp[h]);

    // ---- async loads: u, YB, E1 ----
    {
        uint32_t sb = s2u(sm);
        #pragma unroll
        for (int it = 0; it < 8; it++) {          // u: 2048 x 16B
            int idx = it * 256 + tid;
            int row = idx >> 4, c4 = (idx & 15) << 2;
            const float* src = u + ((size_t)((b0 + (row >> 6)) * NH + h)) * NL
                                 + (row & 63) * 64 + c4;
            cpa16(sb + (P_US + row * 68 + c4) * 4, src);
        }
        const float4* gY = (const float4*)&g_YB[h * 8192];
        #pragma unroll
        for (int it = 0; it < 8; it++) {          // YB: 2048 x 16B
            int idx = it * 256 + tid;
            int row = idx >> 5, c4 = (idx & 31) << 2;
            cpa16(sb + (P_YB + row * 132 + c4) * 4, gY + idx);
        }
        const float4* gE = (const float4*)&g_E1b[h * 4096];
        #pragma unroll
        for (int it = 0; it < 4; it++) {          // E1: 1024 x 16B
            int idx = it * 256 + tid;
            int row = idx >> 4, c4 = (idx & 15) << 2;
            cpa16(sb + (P_CE + row * 68 + c4) * 4, gE + idx);
        }
        asm volatile("cp.async.wait_all;" ::: "memory");
    }
    __syncthreads();

    int m0 = warp * 16;
    int ar = m0 + (lane >> 2);   // A rows: ar, ar+8
    int ac = lane & 3;
    int bn = lane >> 2;          // B n within tile
    int bk2 = (lane & 3) * 2;    // permuted B k offset (float2)

    // ---- P GEMM: P[row][dt] = sum_m U[row][m] * E1[dt][m]  (K=64) ----
    float pc[8][4];
    #pragma unroll
    for (int j = 0; j < 8; j++)
        #pragma unroll
        for (int q = 0; q < 4; q++) pc[j][q] = 0.0f;

    #pragma unroll
    for (int ks = 0; ks < 8; ks++) {
        int k0 = ks * 8;
        uint32_t a0 = f2tf(Us[ar * 68 + k0 + ac]);
        uint32_t a1 = f2tf(Us[(ar + 8) * 68 + k0 + ac]);
        uint32_t a2 = f2tf(Us[ar * 68 + k0 + ac + 4]);
        uint32_t a3 = f2tf(Us[(ar + 8) * 68 + k0 + ac + 4]);
        #pragma unroll
        for (int j = 0; j < 8; j++) {
            float2 bv = *(float2*)&E1s[(j * 8 + bn) * 68 + k0 + bk2];
            mma8(pc[j], a0, a1, a2, a3, __float_as_uint(bv.x), __float_as_uint(bv.y));
        }
    }
    __syncthreads();   // all E1s reads done before region is reused as CPs

    // write P into CPs (natural dt order)
    {
        int ra = m0 + (lane >> 2);
        #pragma unroll
        for (int j = 0; j < 8; j++) {
            int col = j * 8 + 2 * (lane & 3);
            *(float2*)&CPs[ra * 68 + col]       = make_float2(pc[j][0], pc[j][1]);
            *(float2*)&CPs[(ra + 8) * 68 + col] = make_float2(pc[j][2], pc[j][3]);
        }
    }
    __syncthreads();

    // ---- carry scan (in place): c_{j+1} = r^64 * c_j + P_j ----
    if (tid < 64) {
        int bl = tid >> 5, d = tid & 31;
        float2 c  = g_c0[h][d];
        float2 rl = g_rL[h][d];
        float* basep = &CPs[(bl * 64) * 68 + 2 * d];
        #pragma unroll 4
        for (int ch = 0; ch < 64; ch++) {
            float2 p = *(float2*)(basep + ch * 68);
            *(float2*)(basep + ch * 68) = c;
            float cr = fmaf(rl.x, c.x, fmaf(-rl.y, c.y, p.x));
            float ci = fmaf(rl.x, c.y, fmaf( rl.y, c.x, p.y));
            c = make_float2(cr, ci);
        }
    }
    __syncthreads();

    // ---- Y GEMM: y[row][i] = sum_dt C[row][dt]*YB[i][dt] + sum_m U[row][m]*YB[i][64+m] ----
    float yc[8][4];
    #pragma unroll
    for (int j = 0; j < 8; j++)
        #pragma unroll
        for (int q = 0; q < 4; q++) yc[j][q] = 0.0f;

    #pragma unroll
    for (int ks = 0; ks < 8; ks++) {      // K half 1: carries
        int k0 = ks * 8;
        uint32_t a0 = f2tf(CPs[ar * 68 + k0 + ac]);
        uint32_t a1 = f2tf(CPs[(ar + 8) * 68 + k0 + ac]);
        uint32_t a2 = f2tf(CPs[ar * 68 + k0 + ac + 4]);
        uint32_t a3 = f2tf(CPs[(ar + 8) * 68 + k0 + ac + 4]);
        #pragma unroll
        for (int j = 0; j < 8; j++) {
            float2 bv = *(float2*)&YBs[(j * 8 + bn) * 132 + k0 + bk2];
            mma8(yc[j], a0, a1, a2, a3, __float_as_uint(bv.x), __float_as_uint(bv.y));
        }
    }
    #pragma unroll
    for (int ks = 0; ks < 8; ks++) {      // K half 2: u (Toeplitz)
        int k0 = ks * 8;
        uint32_t a0 = f2tf(Us[ar * 68 + k0 + ac]);
        uint32_t a1 = f2tf(Us[(ar + 8) * 68 + k0 + ac]);
        uint32_t a2 = f2tf(Us[ar * 68 + k0 + ac + 4]);
        uint32_t a3 = f2tf(Us[(ar + 8) * 68 + k0 + ac + 4]);
        #pragma unroll
        for (int j = 0; j < 8; j++) {
            float2 bv = *(float2*)&YBs[(j * 8 + bn) * 132 + 64 + k0 + bk2];
            mma8(yc[j], a0, a1, a2, a3, __float_as_uint(bv.x), __float_as_uint(bv.y));
        }
    }

    // ---- epilogue: y = Y + D*u (exact fp32), straight from accumulators ----
    {
        int ra = m0 + (lane >> 2);
        #pragma unroll
        for (int half = 0; half < 2; half++) {
            int r = ra + half * 8;
            float* op = out + ((size_t)((b0 + (r >> 6)) * NH + h)) * NL + (r & 63) * 64;
            #pragma unroll
            for (int j = 0; j < 8; j++) {
                int col = j * 8 + 2 * (lane & 3);
                float2 uv = *(float2*)&Us[r * 68 + col];
                float2 o2;
                o2.x = fmaf(Dv, uv.x, yc[j][half * 2 + 0]);
                o2.y = fmaf(Dv, uv.y, yc[j][half * 2 + 1]);
                *(float2*)(op + col) = o2;
            }
        }
    }
}

// ---------------------------------------------------------------------------
extern "C" void kernel_launch(void* const* d_in, const int* in_sizes, int n_in,
                              void* d_out, int out_size) {
    (void)in_sizes; (void)n_in; (void)out_size;
    const float* u     = (const float*)d_in[0];
    const float* theta = (const float*)d_in[1];
    const float* a     = (const float*)d_in[2];
    const float* Dp    = (const float*)d_in[3];
    const float* b_p   = (const float*)d_in[4];
    const float* c_p   = (const float*)d_in[5];
    const float* x0    = (const float*)d_in[6];
    float* out = (float*)d_out;

    cudaFuncSetAttribute(k_fused, cudaFuncAttributeMaxDynamicSharedMemorySize, SMEMF);

    k_setup<<<NH, 128>>>(theta, a, b_p, c_p, x0);
    k_fused<<<1024, 256, SMEMF>>>(u, Dp, out);
}

// round 5
// speedup vs baseline: 3.0053x; 1.1999x over previous
#include <cuda_runtime.h>
#include <cstdint>

#define NH 256
#define NL 4096
#define AP 132                 // As pitch in floats (132 mod 32 banks = 4 -> conflict-free)
#define YBOFF (128 * AP)       // YBs offset (floats) = 16896
#define NFLT  (YBOFF + 64 * AP)
#define SMEMF (NFLT * 4)       // 101376 B -> 2 CTAs/SM

static __device__ __forceinline__ int kperm(int k) {
    return (k & ~7) | ((k & 3) << 1) | ((k >> 2) & 1);
}
static __device__ __forceinline__ uint32_t s2u(const void* p) {
    uint32_t a;
    asm("{ .reg .u64 t; cvta.to.shared.u64 t, %1; cvt.u32.u64 %0, t; }" : "=r"(a) : "l"(p));
    return a;
}
static __device__ __forceinline__ void cpa16(uint32_t dst, const void* src) {
    asm volatile("cp.async.cg.shared.global [%0], [%1], 16;" :: "r"(dst), "l"(src) : "memory");
}
static __device__ __forceinline__ void ldmA(uint32_t* a, uint32_t addr) {
    asm volatile("ldmatrix.sync.aligned.m8n8.x4.shared.b16 {%0,%1,%2,%3}, [%4];"
                 : "=r"(a[0]), "=r"(a[1]), "=r"(a[2]), "=r"(a[3]) : "r"(addr));
}
static __device__ __forceinline__ void mma8(float* c, const uint32_t* a, float2 bv) {
    asm volatile(
        "mma.sync.aligned.m16n8k8.row.col.f32.tf32.tf32.f32 "
        "{%0,%1,%2,%3},{%4,%5,%6,%7},{%8,%9},{%0,%1,%2,%3};"
        : "+f"(c[0]), "+f"(c[1]), "+f"(c[2]), "+f"(c[3])
        : "r"(a[0]), "r"(a[1]), "r"(a[2]), "r"(a[3]),
          "r"(__float_as_uint(bv.x)), "r"(__float_as_uint(bv.y)));
}

// ---------------------------------------------------------------------------
// Single fused kernel. CTA = (h, b-pair).
// SMEM map (floats):
//  As[128][AP] @0: cols 0-63 = u (persistent).
//   cols 64-131 time-shared:  rows 0-63 = E1 tile; rows 64-127 = r^p table
//   (r^p, p in [1,64], at As[(63+p)*AP + 64 + 2d]);  later rows 0-127
//   cols 64-127 = P / carries.
//  YBs[64][AP] @YBOFF: Y-GEMM B operand.
// Phases: cp.async u | params+r^p | sf+E1 | P GEMM | YB build | P write |
//         scan | Y GEMM | epilogue (+D*u)
// ---------------------------------------------------------------------------
__global__ __launch_bounds__(256, 2) void k_fused(
        const float* __restrict__ u,     const float* __restrict__ theta,
        const float* __restrict__ av_,   const float* __restrict__ Dp,
        const float* __restrict__ b_p,   const float* __restrict__ c_p,
        const float* __restrict__ x0,    float* __restrict__ out) {
    extern __shared__ float sm[];
    float* As  = sm;
    float* YBs = sm + YBOFF;
    __shared__ float2 swS[32];
    __shared__ float2 c0S[32];
    __shared__ float  sfS[64];

    int tid  = threadIdx.x;
    int lane = tid & 31, warp = tid >> 5;
    int mw = warp & 3, nw = warp >> 2;          // 4(M) x 2(N) warp grid
    int h = blockIdx.x >> 2, b0 = (blockIdx.x & 3) * 2;
    const float T = 1.0f / (float)(NL - 1);
    float Dv = __ldg(&Dp[h]);
    uint32_t sb = s2u(sm);

    // ---- phase 0: async u loads ----
    #pragma unroll
    for (int it = 0; it < 8; it++) {
        int idx = it * 256 + tid;
        int row = idx >> 4, c4 = (idx & 15) << 2;
        const float* src = u + ((size_t)((b0 + (row >> 6)) * NH + h)) * NL
                             + (row & 63) * 64 + c4;
        cpa16(sb + (row * AP + c4) * 4, src);
    }

    // ---- phase 0b: per-d params (w, c0) ----
    if (tid < 32) {
        int d = tid, idx = h * 32 + d;
        float av = fabsf(av_[idx]);
        float th = theta[idx];
        float er = expf(-av * T);
        float rr = er * cosf(th * T), ri = er * sinf(th * T);
        float den = av * av + th * th;
        float nr = rr - 1.0f, ni = ri;
        float t0r = (nr * -av + ni * th) / den;
        float t0i = (ni * -av - nr * th) / den;
        float q = b_p[idx] * c_p[idx];
        swS[d] = make_float2(2.0f * t0r * q, 2.0f * t0i * q);
        float g = 4.0f * T * c_p[idx] * x0[idx];
        float rm2 = rr * rr + ri * ri;
        c0S[d] = make_float2(g * rr / rm2, -g * ri / rm2);
    }
    // ---- r^p table, p in [1,64] (direct eval, no serial chain) ----
    #pragma unroll
    for (int it = 0; it < 8; it++) {
        int e = it * 256 + tid;               // 2048
        int pm1 = e >> 5, d = e & 31;
        float av = fabsf(av_[h * 32 + d]);
        float th = theta[h * 32 + d];
        float tt = T * (float)(pm1 + 1);
        float ex = expf(-av * tt);
        float s, c;
        sincosf(th * tt, &s, &c);
        *(float2*)&As[(64 + pm1) * AP + 64 + 2 * d] = make_float2(ex * c, ex * s);
    }
    __syncthreads();

    // ---- sf filter + E1 tile ----
    if (tid < 64) {
        int j = tid;
        float s = 0.0f;
        #pragma unroll
        for (int d = 0; d < 32; d++) {
            float2 w = swS[d];
            float2 rv = j ? *(float2*)&As[(63 + j) * AP + 64 + 2 * d]
                          : make_float2(1.0f, 0.0f);
            s += w.x * rv.x - w.y * rv.y;
        }
        sfS[j] = s;
    }
    #pragma unroll
    for (int it = 0; it < 8; it++) {
        int e = it * 256 + tid;               // 2048 (d, m) pairs
        int d = e >> 6, m = e & 63;
        float2 w = swS[d];
        float2 rv = (m == 63) ? make_float2(1.0f, 0.0f)
                              : *(float2*)&As[(126 - m) * AP + 64 + 2 * d];
        int col = 64 + kperm(m);
        As[(2 * d) * AP + col]     = w.x * rv.x - w.y * rv.y;
        As[(2 * d + 1) * AP + col] = w.x * rv.y + w.y * rv.x;
    }
    asm volatile("cp.async.wait_all;" ::: "memory");
    __syncthreads();

    // ---- fragment addressing ----
    uint32_t aB[2];
    #pragma unroll
    for (int mt = 0; mt < 2; mt++)
        aB[mt] = sb + ((mw * 32 + mt * 16 + (lane & 7) + ((lane >> 3) & 1) * 8) * AP) * 4
                    + ((lane >> 4) & 1) * 16;
    int bRow  = nw * 32 + (lane >> 2);
    int bCol2 = 2 * (lane & 3);

    // ---- P GEMM: P[row][dt] = sum_m U[row][m] * E1[dt][m], K=64 ----
    float pc[2][4][4];
    #pragma unroll
    for (int mt = 0; mt < 2; mt++)
        #pragma unroll
        for (int j = 0; j < 4; j++)
            #pragma unroll
            for (int q = 0; q < 4; q++) pc[mt][j][q] = 0.0f;

    #pragma unroll
    for (int ks = 0; ks < 8; ks++) {
        int k0 = ks * 8;
        uint32_t a[2][4];
        ldmA(a[0], aB[0] + k0 * 4);
        ldmA(a[1], aB[1] + k0 * 4);
        #pragma unroll
        for (int j = 0; j < 4; j++) {
            float2 bv = *(float2*)&As[(bRow + j * 8) * AP + 64 + k0 + bCol2];
            mma8(pc[0][j], a[0], bv);
            mma8(pc[1][j], a[1], bv);
        }
    }

    // ---- build YB tile (reads r^p + sf; writes YBs only -- no hazard w/ P GEMM) ----
    #pragma unroll
    for (int it = 0; it < 32; it++) {
        int e = it * 256 + tid;               // 8192
        int i = e >> 7, k = e & 127;
        float v;
        if (k < 64) {
            float2 rv = *(float2*)&As[(64 + i) * AP + 64 + ((k >> 1) << 1)];
            v = (k & 1) ? -rv.y : rv.x;
        } else {
            int m = k - 64;
            v = (i > m) ? sfS[i - m] : ((i == m) ? sfS[0] : 0.0f);
        }
        YBs[i * AP + kperm(k)] = v;
    }
    float2 rl;
    if (tid < 64)
        rl = *(float2*)&As[127 * AP + 64 + 2 * (tid & 31)];   // r^64
    __syncthreads();   // all E1/r^p reads done before carries overwrite

    // ---- write P frags into carry region ----
    #pragma unroll
    for (int mt = 0; mt < 2; mt++)
        #pragma unroll
        for (int j = 0; j < 4; j++) {
            int ra  = mw * 32 + mt * 16 + (lane >> 2);
            int col = 64 + nw * 32 + j * 8 + 2 * (lane & 3);
            *(float2*)&As[ra * AP + col]       = make_float2(pc[mt][j][0], pc[mt][j][1]);
            *(float2*)&As[(ra + 8) * AP + col] = make_float2(pc[mt][j][2], pc[mt][j][3]);
        }
    __syncthreads();

    // ---- carry scan (in place): c_{j+1} = r^64 * c_j + P_j ----
    if (tid < 64) {
        int bl = tid >> 5, d = tid & 31;
        float2 c = c0S[d];
        float* basep = &As[(bl * 64) * AP + 64 + 2 * d];
        #pragma unroll 4
        for (int ch = 0; ch < 64; ch++) {
            float2 p = *(float2*)(basep + ch * AP);
            *(float2*)(basep + ch * AP) = c;
            float cr = fmaf(rl.x, c.x, fmaf(-rl.y, c.y, p.x));
            float ci = fmaf(rl.x, c.y, fmaf( rl.y, c.x, p.y));
            c = make_float2(cr, ci);
        }
    }
    __syncthreads();

    // ---- Y GEMM: y = C . YB[:,0:64] + U . YB[:,64:128]  (K=128) ----
    float yc[2][4][4];
    #pragma unroll
    for (int mt = 0; mt < 2; mt++)
        #pragma unroll
        for (int j = 0; j < 4; j++)
            #pragma unroll
            for (int q = 0; q < 4; q++) yc[mt][j][q] = 0.0f;

    #pragma unroll
    for (int ks = 0; ks < 16; ks++) {
        int acol = (ks < 8) ? (64 + ks * 8) : ((ks - 8) * 8);
        int k0 = ks * 8;
        uint32_t a[2][4];
        ldmA(a[0], aB[0] + acol * 4);
        ldmA(a[1], aB[1] + acol * 4);
        #pragma unroll
        for (int j = 0; j < 4; j++) {
            float2 bv = *(float2*)&YBs[(bRow + j * 8) * AP + k0 + bCol2];
            mma8(yc[0][j], a[0], bv);
            mma8(yc[1][j], a[1], bv);
        }
    }

    // ---- epilogue: y = Y + D*u (exact fp32) ----
    #pragma unroll
    for (int mt = 0; mt < 2; mt++)
        #pragma unroll
        for (int half = 0; half < 2; half++) {
            int r = mw * 32 + mt * 16 + (lane >> 2) + half * 8;
            float* op = out + ((size_t)((b0 + (r >> 6)) * NH + h)) * NL + (r & 63) * 64;
            #pragma unroll
            for (int j = 0; j < 4; j++) {
                int col = nw * 32 + j * 8 + 2 * (lane & 3);
                float2 uv = *(float2*)&As[r * AP + col];
                float2 o2;
                o2.x = fmaf(Dv, uv.x, yc[mt][j][half * 2 + 0]);
                o2.y = fmaf(Dv, uv.y, yc[mt][j][half * 2 + 1]);
                *(float2*)(op + col) = o2;
            }
        }
}

// ---------------------------------------------------------------------------
extern "C" void kernel_launch(void* const* d_in, const int* in_sizes, int n_in,
                              void* d_out, int out_size) {
    (void)in_sizes; (void)n_in; (void)out_size;
    const float* u     = (const float*)d_in[0];
    const float* theta = (const float*)d_in[1];
    const float* a     = (const float*)d_in[2];
    const float* Dp    = (const float*)d_in[3];
    const float* b_p   = (const float*)d_in[4];
    const float* c_p   = (const float*)d_in[5];
    const float* x0    = (const float*)d_in[6];
    float* out = (float*)d_out;

    cudaFuncSetAttribute(k_fused, cudaFuncAttributeMaxDynamicSharedMemorySize, SMEMF);
    k_fused<<<1024, 256, SMEMF>>>(u, theta, a, Dp, b_p, c_p, x0, out);
}

// round 6
// speedup vs baseline: 3.6494x; 1.2143x over previous
#include <cuda_runtime.h>
#include <cstdint>

#define NH 256
#define NL 4096
#define AP 68                  // pitch (floats): mult of 4 (ldmatrix 16B rows), 68%32=4 spreads banks
#define CROFF  (128 * AP)      // carries / E1 region
#define INJOFF (256 * AP)      // injection table r^p in B-operand layout
#define NFLT   (INJOFF + 64 * AP)
#define SMEMF  (NFLT * 4)      // 87040 B -> 2 CTAs/SM

static __device__ __forceinline__ int kperm(int k) {
    return (k & ~7) | ((k & 3) << 1) | ((k >> 2) & 1);
}
static __device__ __forceinline__ uint32_t s2u(const void* p) {
    uint32_t a;
    asm("{ .reg .u64 t; cvta.to.shared.u64 t, %1; cvt.u32.u64 %0, t; }" : "=r"(a) : "l"(p));
    return a;
}
static __device__ __forceinline__ void cpa16(uint32_t dst, const void* src) {
    asm volatile("cp.async.cg.shared.global [%0], [%1], 16;" :: "r"(dst), "l"(src) : "memory");
}
static __device__ __forceinline__ void ldmA(uint32_t* a, uint32_t addr) {
    asm volatile("ldmatrix.sync.aligned.m8n8.x4.shared.b16 {%0,%1,%2,%3}, [%4];"
                 : "=r"(a[0]), "=r"(a[1]), "=r"(a[2]), "=r"(a[3]) : "r"(addr));
}
static __device__ __forceinline__ void mma8(float* c, const uint32_t* a, float bx, float by) {
    asm volatile(
        "mma.sync.aligned.m16n8k8.row.col.f32.tf32.tf32.f32 "
        "{%0,%1,%2,%3},{%4,%5,%6,%7},{%8,%9},{%0,%1,%2,%3};"
        : "+f"(c[0]), "+f"(c[1]), "+f"(c[2]), "+f"(c[3])
        : "r"(a[0]), "r"(a[1]), "r"(a[2]), "r"(a[3]),
          "r"(__float_as_uint(bx)), "r"(__float_as_uint(by)));
}
static __device__ __forceinline__ float2 cmad(float2 m, float2 c, float2 p) {
    // m*c + p (complex)
    float2 r;
    r.x = fmaf(m.x, c.x, fmaf(-m.y, c.y, p.x));
    r.y = fmaf(m.x, c.y, fmaf( m.y, c.x, p.y));
    return r;
}

// ---------------------------------------------------------------------------
// Single fused kernel. CTA = (h, b-pair), M=128 rows.
// SMEM (floats): Us[128][AP] @0 (u), CR[128][AP] @CROFF (E1 rows0-63 -> P/carries),
//                Inj[64][AP] @INJOFF (r^{i+1} in B-operand layout, odd cols = -Im).
// ---------------------------------------------------------------------------
__global__ __launch_bounds__(256, 2) void k_fused(
        const float* __restrict__ u,     const float* __restrict__ theta,
        const float* __restrict__ av_,   const float* __restrict__ Dp,
        const float* __restrict__ b_p,   const float* __restrict__ c_p,
        const float* __restrict__ x0,    float* __restrict__ out) {
    extern __shared__ float sm[];
    float* Us  = sm;
    float* CR  = sm + CROFF;
    float* Inj = sm + INJOFF;
    __shared__ float2 swS[32];
    __shared__ float2 c0S[32];
    __shared__ float  sfX[128];
    __shared__ float2 Sbuf[4][64];

    int tid  = threadIdx.x;
    int lane = tid & 31, warp = tid >> 5;
    int mw = warp & 3, nw = warp >> 2;          // 4(M) x 2(N) warp grid
    int h = blockIdx.x >> 2, b0 = (blockIdx.x & 3) * 2;
    const float T = 1.0f / (float)(NL - 1);
    float Dv = __ldg(&Dp[h]);
    uint32_t sb = s2u(sm);

    // ---- phase 0: async u loads ----
    #pragma unroll
    for (int it = 0; it < 8; it++) {
        int idx = it * 256 + tid;
        int row = idx >> 4, c4 = (idx & 15) << 2;
        const float* src = u + ((size_t)((b0 + (row >> 6)) * NH + h)) * NL
                             + (row & 63) * 64 + c4;
        cpa16(sb + (row * AP + c4) * 4, src);
    }

    // ---- phase 0b: params + power chain (32 transcendental calls total) ----
    if (tid < 32) {
        int d = tid, idx = h * 32 + d;
        float av = fabsf(av_[idx]);
        float th = theta[idx];
        float er = expf(-av * T);
        float rr = er * cosf(th * T), ri = er * sinf(th * T);
        float den = av * av + th * th;
        float nr = rr - 1.0f, ni = ri;
        float t0r = (nr * -av + ni * th) / den;
        float t0i = (ni * -av - nr * th) / den;
        float q = b_p[idx] * c_p[idx];
        swS[d] = make_float2(2.0f * t0r * q, 2.0f * t0i * q);
        float g = 4.0f * T * c_p[idx] * x0[idx];
        float rm2 = rr * rr + ri * ri;
        c0S[d] = make_float2(g * rr / rm2, -g * ri / rm2);
        // chain r^1..r^64 into Inj (row p-1), B-operand layout, odd col = -Im
        int kpE = kperm(2 * d), kpO = kperm(2 * d + 1);
        float pr = rr, pi = ri;
        Inj[kpE] = pr; Inj[kpO] = -pi;
        for (int p = 2; p <= 64; p++) {
            float npr = fmaf(pr, rr, -pi * ri);
            float npi = fmaf(pr, ri,  pi * rr);
            pr = npr; pi = npi;
            Inj[(p - 1) * AP + kpE] = pr;
            Inj[(p - 1) * AP + kpO] = -pi;
        }
    }
    __syncthreads();

    // ---- E1 tile build into CR rows 0-63 (B-operand layout, m k-permuted) ----
    #pragma unroll
    for (int it = 0; it < 8; it++) {
        int e = it * 256 + tid;               // 2048 (d, m)
        int d = e >> 6, m = e & 63;
        float2 w = swS[d];
        float re, mi;                          // r^{63-m} = (re, -mi)
        if (m == 63) { re = 1.0f; mi = 0.0f; }
        else {
            re = Inj[(62 - m) * AP + kperm(2 * d)];
            mi = Inj[(62 - m) * AP + kperm(2 * d + 1)];
        }
        int col = kperm(m);
        CR[(2 * d) * AP + col]     = fmaf(w.x, re,  w.y * mi);
        CR[(2 * d + 1) * AP + col] = fmaf(w.y, re, -w.x * mi);
    }
    // ---- sfX: zero pad [0,64) + filter f[j] at [64+j] ----
    if (tid < 128) {
        if (tid < 64) sfX[tid] = 0.0f;
        else {
            int j = tid - 64;
            float s = 0.0f;
            if (j == 0) {
                #pragma unroll
                for (int d = 0; d < 32; d++) s += swS[d].x;
            } else {
                #pragma unroll
                for (int d = 0; d < 32; d++) {
                    float2 w = swS[d];
                    s = fmaf(w.x, Inj[(j - 1) * AP + kperm(2 * d)],
                        fmaf(w.y, Inj[(j - 1) * AP + kperm(2 * d + 1)], s));
                }
            }
            sfX[tid] = s;
        }
    }
    asm volatile("cp.async.wait_all;" ::: "memory");
    __syncthreads();

    // ---- fragment addressing ----
    uint32_t aU[2], aC[2];
    #pragma unroll
    for (int mt = 0; mt < 2; mt++) {
        uint32_t off = ((mw * 32 + mt * 16 + (lane & 7) + ((lane >> 3) & 1) * 8) * AP) * 4
                       + ((lane >> 4) & 1) * 16;
        aU[mt] = sb + off;
        aC[mt] = sb + CROFF * 4 + off;
    }
    int bRow  = nw * 32 + (lane >> 2);
    int bCol2 = 2 * (lane & 3);

    // ---- P GEMM: P[row][dt] = sum_m U[row][m] * E1[dt][m], K=64 ----
    float pc[2][4][4];
    #pragma unroll
    for (int mt = 0; mt < 2; mt++)
        #pragma unroll
        for (int j = 0; j < 4; j++)
            #pragma unroll
            for (int q = 0; q < 4; q++) pc[mt][j][q] = 0.0f;

    #pragma unroll
    for (int ks = 0; ks < 8; ks++) {
        int k0 = ks * 8;
        uint32_t a[2][4];
        ldmA(a[0], aU[0] + k0 * 4);
        ldmA(a[1], aU[1] + k0 * 4);
        #pragma unroll
        for (int j = 0; j < 4; j++) {
            float2 bv = *(float2*)&CR[(bRow + j * 8) * AP + k0 + bCol2];
            mma8(pc[0][j], a[0], bv.x, bv.y);
            mma8(pc[1][j], a[1], bv.x, bv.y);
        }
    }
    __syncthreads();   // all E1 reads done before region reused for P/carries

    // ---- write P frags (natural dt cols 0-63 of CR) ----
    #pragma unroll
    for (int mt = 0; mt < 2; mt++)
        #pragma unroll
        for (int j = 0; j < 4; j++) {
            int ra  = mw * 32 + mt * 16 + (lane >> 2);
            int col = nw * 32 + j * 8 + 2 * (lane & 3);
            *(float2*)&CR[ra * AP + col]       = make_float2(pc[mt][j][0], pc[mt][j][1]);
            *(float2*)&CR[(ra + 8) * AP + col] = make_float2(pc[mt][j][2], pc[mt][j][3]);
        }
    __syncthreads();

    // ---- parallel carry scan: 64 sequences x 64 chunks, 4 threads/sequence ----
    {
        int t = tid >> 6, seq = tid & 63;       // t uniform per warp-pair
        int bl = seq >> 5, d = seq & 31;
        float2 rl = make_float2( Inj[63 * AP + kperm(2 * d)],
                                -Inj[63 * AP + kperm(2 * d + 1)]);   // r^64
        float2 R = rl;                           // R = rl^16
        #pragma unroll
        for (int sq = 0; sq < 4; sq++) {
            float2 nR;
            nR.x = fmaf(R.x, R.x, -R.y * R.y);
            nR.y = 2.0f * R.x * R.y;
            R = nR;
        }
        float* bp = &CR[(bl * 64 + t * 16) * AP + 2 * d];
        float2 s = make_float2(0.0f, 0.0f);
        #pragma unroll
        for (int i = 0; i < 16; i++)
            s = cmad(rl, s, *(float2*)(bp + i * AP));
        Sbuf[t][seq] = s;
        __syncthreads();
        float2 X = c0S[d];
        for (int k = 0; k < t; k++)             // t uniform per warp: no divergence
            X = cmad(R, X, Sbuf[k][seq]);
        #pragma unroll
        for (int i = 0; i < 16; i++) {
            float2 p = *(float2*)(bp + i * AP);
            *(float2*)(bp + i * AP) = X;
            X = cmad(rl, X, p);
        }
    }
    __syncthreads();

    // ---- Y GEMM: y = C . Inj + U . Toeplitz(sfX)  (K=128) ----
    float yc[2][4][4];
    #pragma unroll
    for (int mt = 0; mt < 2; mt++)
        #pragma unroll
        for (int j = 0; j < 4; j++)
            #pragma unroll
            for (int q = 0; q < 4; q++) yc[mt][j][q] = 0.0f;

    #pragma unroll
    for (int ks = 0; ks < 8; ks++) {            // half 1: carries x injection
        int k0 = ks * 8;
        uint32_t a[2][4];
        ldmA(a[0], aC[0] + k0 * 4);
        ldmA(a[1], aC[1] + k0 * 4);
        #pragma unroll
        for (int j = 0; j < 4; j++) {
            float2 bv = *(float2*)&Inj[(bRow + j * 8) * AP + k0 + bCol2];
            mma8(yc[0][j], a[0], bv.x, bv.y);
            mma8(yc[1][j], a[1], bv.x, bv.y);
        }
    }
    {                                            // half 2: u x Toeplitz (on-the-fly B)
        int tb = 64 + nw * 32 + (lane >> 2) - (lane & 3);
        #pragma unroll
        for (int ks = 0; ks < 8; ks++) {
            int k0 = ks * 8;
            uint32_t a[2][4];
            ldmA(a[0], aU[0] + k0 * 4);
            ldmA(a[1], aU[1] + k0 * 4);
            #pragma unroll
            for (int j = 0; j < 4; j++) {
                int ix = tb + j * 8 - k0;
                float bx = sfX[ix], by = sfX[ix - 4];
                mma8(yc[0][j], a[0], bx, by);
                mma8(yc[1][j], a[1], bx, by);
            }
        }
    }

    // ---- epilogue: y = Y + D*u (exact fp32) ----
    #pragma unroll
    for (int mt = 0; mt < 2; mt++)
        #pragma unroll
        for (int half = 0; half < 2; half++) {
            int r = mw * 32 + mt * 16 + (lane >> 2) + half * 8;
            float* op = out + ((size_t)((b0 + (r >> 6)) * NH + h)) * NL + (r & 63) * 64;
            #pragma unroll
            for (int j = 0; j < 4; j++) {
                int col = nw * 32 + j * 8 + 2 * (lane & 3);
                float2 uv = *(float2*)&Us[r * AP + col];
                float2 o2;
                o2.x = fmaf(Dv, uv.x, yc[mt][j][half * 2 + 0]);
                o2.y = fmaf(Dv, uv.y, yc[mt][j][half * 2 + 1]);
                *(float2*)(op + col) = o2;
            }
        }
}

// ---------------------------------------------------------------------------
extern "C" void kernel_launch(void* const* d_in, const int* in_sizes, int n_in,
                              void* d_out, int out_size) {
    (void)in_sizes; (void)n_in; (void)out_size;
    const float* u     = (const float*)d_in[0];
    const float* theta = (const float*)d_in[1];
    const float* a     = (const float*)d_in[2];
    const float* Dp    = (const float*)d_in[3];
    const float* b_p   = (const float*)d_in[4];
    const float* c_p   = (const float*)d_in[5];
    const float* x0    = (const float*)d_in[6];
    float* out = (float*)d_out;

    cudaFuncSetAttribute(k_fused, cudaFuncAttributeMaxDynamicSharedMemorySize, SMEMF);
    k_fused<<<1024, 256, SMEMF>>>(u, theta, a, Dp, b_p, c_p, x0, out);
}

// round 7
// speedup vs baseline: 3.6523x; 1.0008x over previous
#include <cuda_runtime.h>
#include <cstdint>

#define NH 256
#define NL 4096
#define AP 68                  // pitch (floats): mult of 4 (ldmatrix 16B rows), 68%32=4 spreads banks
#define CROFF  (128 * AP)      // E1 -> P/carries region
#define INJOFF (256 * AP)      // injection table r^p in B-operand layout
#define NFLT   (INJOFF + 64 * AP)
#define SMEMF  (NFLT * 4)      // 87040 B -> 2 CTAs/SM

static __device__ __forceinline__ int kperm(int k) {
    return (k & ~7) | ((k & 3) << 1) | ((k >> 2) & 1);
}
static __device__ __forceinline__ uint32_t s2u(const void* p) {
    uint32_t a;
    asm("{ .reg .u64 t; cvta.to.shared.u64 t, %1; cvt.u32.u64 %0, t; }" : "=r"(a) : "l"(p));
    return a;
}
static __device__ __forceinline__ void cpa16(uint32_t dst, const void* src) {
    asm volatile("cp.async.cg.shared.global [%0], [%1], 16;" :: "r"(dst), "l"(src) : "memory");
}
static __device__ __forceinline__ void ldmA(uint32_t* a, uint32_t addr) {
    asm volatile("ldmatrix.sync.aligned.m8n8.x4.shared.b16 {%0,%1,%2,%3}, [%4];"
                 : "=r"(a[0]), "=r"(a[1]), "=r"(a[2]), "=r"(a[3]) : "r"(addr));
}
static __device__ __forceinline__ void mma8(float* c, const uint32_t* a, float bx, float by) {
    asm volatile(
        "mma.sync.aligned.m16n8k8.row.col.f32.tf32.tf32.f32 "
        "{%0,%1,%2,%3},{%4,%5,%6,%7},{%8,%9},{%0,%1,%2,%3};"
        : "+f"(c[0]), "+f"(c[1]), "+f"(c[2]), "+f"(c[3])
        : "r"(a[0]), "r"(a[1]), "r"(a[2]), "r"(a[3]),
          "r"(__float_as_uint(bx)), "r"(__float_as_uint(by)));
}
static __device__ __forceinline__ float2 cmad(float2 m, float2 c, float2 p) {
    float2 r;
    r.x = fmaf(m.x, c.x, fmaf(-m.y, c.y, p.x));
    r.y = fmaf(m.x, c.y, fmaf( m.y, c.x, p.y));
    return r;
}

// ---------------------------------------------------------------------------
// Single fused kernel. CTA = (h, b-pair), M=128 rows.
// SMEM (floats): Us[128][AP] @0 (u), CR[128][AP] @CROFF (E1 rows0-63 -> P/carries),
//                Inj[64][AP] @INJOFF (r^{i+1} in B-operand layout, odd cols = -Im).
// ---------------------------------------------------------------------------
__global__ __launch_bounds__(256, 2) void k_fused(
        const float* __restrict__ u,     const float* __restrict__ theta,
        const float* __restrict__ av_,   const float* __restrict__ Dp,
        const float* __restrict__ b_p,   const float* __restrict__ c_p,
        const float* __restrict__ x0,    float* __restrict__ out) {
    extern __shared__ float sm[];
    float* Us  = sm;
    float* CR  = sm + CROFF;
    float* Inj = sm + INJOFF;
    __shared__ float2 swS[32];
    __shared__ float2 c0S[32];
    __shared__ float  sfX[128];
    __shared__ float2 Sbuf[4][64];
    __shared__ float2 R8S[8][32];   // (r^8)^k, k=1..8, at [k-1][d]

    int tid  = threadIdx.x;
    int lane = tid & 31, warp = tid >> 5;
    int mw = warp & 3, nw = warp >> 2;          // 4(M) x 2(N) warp grid
    int h = blockIdx.x >> 2, b0 = (blockIdx.x & 3) * 2;
    const float T = 1.0f / (float)(NL - 1);
    float Dv = __ldg(&Dp[h]);
    uint32_t sb = s2u(sm);

    // ---- phase 0: async u loads ----
    #pragma unroll
    for (int it = 0; it < 8; it++) {
        int idx = it * 256 + tid;
        int row = idx >> 4, c4 = (idx & 15) << 2;
        const float* src = u + ((size_t)((b0 + (row >> 6)) * NH + h)) * NL
                             + (row & 63) * 64 + c4;
        cpa16(sb + (row * AP + c4) * 4, src);
    }

    // ---- phase A: params + short chains (14 serial cmuls, warp 0 only) ----
    if (tid < 32) {
        int d = tid, idx = h * 32 + d;
        float av = fabsf(av_[idx]);
        float th = theta[idx];
        float er = expf(-av * T);
        float rr = er * cosf(th * T), ri = er * sinf(th * T);
        float den = av * av + th * th;
        float nr = rr - 1.0f, ni = ri;
        float t0r = (nr * -av + ni * th) / den;
        float t0i = (ni * -av - nr * th) / den;
        float q = b_p[idx] * c_p[idx];
        swS[d] = make_float2(2.0f * t0r * q, 2.0f * t0i * q);
        float g = 4.0f * T * c_p[idx] * x0[idx];
        float rm2 = rr * rr + ri * ri;
        c0S[d] = make_float2(g * rr / rm2, -g * ri / rm2);
        int kpE = kperm(2 * d), kpO = kperm(2 * d + 1);
        // r^1..r^8 into Inj rows 0..7
        float pr = rr, pi = ri;
        Inj[kpE] = pr; Inj[kpO] = -pi;
        #pragma unroll
        for (int p = 2; p <= 8; p++) {
            float npr = fmaf(pr, rr, -pi * ri);
            float npi = fmaf(pr, ri,  pi * rr);
            pr = npr; pi = npi;
            Inj[(p - 1) * AP + kpE] = pr;
            Inj[(p - 1) * AP + kpO] = -pi;
        }
        // (r^8)^k, k=1..8
        float qr = pr, qi = pi;
        R8S[0][d] = make_float2(qr, qi);
        #pragma unroll
        for (int k = 2; k <= 8; k++) {
            float nqr = fmaf(qr, pr, -qi * pi);
            float nqi = fmaf(qr, pi,  qi * pr);
            qr = nqr; qi = nqi;
            R8S[k - 1][d] = make_float2(qr, qi);
        }
    }
    __syncthreads();

    // ---- phase C: fill Inj rows 8..63 (one cmul each, 256 threads) ----
    #pragma unroll
    for (int it = 0; it < 7; it++) {
        int e = it * 256 + tid;               // 1792 = 56 rows x 32 d
        int i = 8 + (e >> 5), d = e & 31;
        int kpE = kperm(2 * d), kpO = kperm(2 * d + 1);
        int v = i + 1;                        // 9..64
        int k = (v - 1) >> 3, j = v - (k << 3);   // v = 8k + j, j in 1..8
        float2 A = R8S[k - 1][d];
        float bRe = Inj[(j - 1) * AP + kpE];
        float bIm = -Inj[(j - 1) * AP + kpO];
        float re = fmaf(A.x, bRe, -A.y * bIm);
        float im = fmaf(A.x, bIm,  A.y * bRe);
        Inj[i * AP + kpE] = re;
        Inj[i * AP + kpO] = -im;
    }
    __syncthreads();

    // ---- E1 tile into CR rows 0-63 (B-operand layout) ----
    #pragma unroll
    for (int it = 0; it < 8; it++) {
        int e = it * 256 + tid;               // 2048 (d, m)
        int d = e >> 6, m = e & 63;
        float2 w = swS[d];
        float re, mi;                          // r^{63-m} = (re, -mi)
        if (m == 63) { re = 1.0f; mi = 0.0f; }
        else {
            re = Inj[(62 - m) * AP + kperm(2 * d)];
            mi = Inj[(62 - m) * AP + kperm(2 * d + 1)];
        }
        int col = kperm(m);
        CR[(2 * d) * AP + col]     = fmaf(w.x, re,  w.y * mi);
        CR[(2 * d + 1) * AP + col] = fmaf(w.y, re, -w.x * mi);
    }
    // ---- sfX: zero pad [0,64) + filter f[j] at [64+j] ----
    if (tid < 128) {
        if (tid < 64) sfX[tid] = 0.0f;
        else {
            int j = tid - 64;
            float s = 0.0f;
            if (j == 0) {
                #pragma unroll
                for (int d = 0; d < 32; d++) s += swS[d].x;
            } else {
                #pragma unroll
                for (int d = 0; d < 32; d++) {
                    float2 w = swS[d];
                    s = fmaf(w.x, Inj[(j - 1) * AP + kperm(2 * d)],
                        fmaf(w.y, Inj[(j - 1) * AP + kperm(2 * d + 1)], s));
                }
            }
            sfX[tid] = s;
        }
    }
    asm volatile("cp.async.wait_all;" ::: "memory");
    __syncthreads();

    // ---- fragment addressing ----
    uint32_t aU[2], aC[2];
    #pragma unroll
    for (int mt = 0; mt < 2; mt++) {
        uint32_t off = ((mw * 32 + mt * 16 + (lane & 7) + ((lane >> 3) & 1) * 8) * AP) * 4
                       + ((lane >> 4) & 1) * 16;
        aU[mt] = sb + off;
        aC[mt] = sb + CROFF * 4 + off;
    }
    int bRowP = nw * 32 + (lane >> 2);          // P GEMM N(dt) mapping (unchanged)
    int bCol2 = 2 * (lane & 3);
    int bn8   = lane >> 2;                       // n within 8-tile (Y mapping)

    // ---- merged loop: P GEMM (K=64, dense) + Y half2 (u x Toeplitz, triangle) ----
    float pc[2][4][4], yc[2][4][4];
    #pragma unroll
    for (int mt = 0; mt < 2; mt++)
        #pragma unroll
        for (int j = 0; j < 4; j++)
            #pragma unroll
            for (int q = 0; q < 4; q++) { pc[mt][j][q] = 0.0f; yc[mt][j][q] = 0.0f; }

    #pragma unroll
    for (int ks = 0; ks < 8; ks++) {
        int k0 = ks * 8;
        uint32_t a[2][4];
        ldmA(a[0], aU[0] + k0 * 4);
        ldmA(a[1], aU[1] + k0 * 4);
        #pragma unroll
        for (int j = 0; j < 4; j++) {           // P (E1 in CR)
            float2 bv = *(float2*)&CR[(bRowP + j * 8) * AP + k0 + bCol2];
            mma8(pc[0][j], a[0], bv.x, bv.y);
            mma8(pc[1][j], a[1], bv.x, bv.y);
        }
        #pragma unroll
        for (int j = 0; j < 4; j++) {           // Y half2, skip all-zero blocks
            if (2 * j + nw >= ks) {
                int ix = 64 + (2 * j + nw) * 8 + bn8 - (lane & 3) - k0;
                float bx = sfX[ix], by = sfX[ix - 4];
                mma8(yc[0][j], a[0], bx, by);
                mma8(yc[1][j], a[1], bx, by);
            }
        }
    }
    __syncthreads();   // all E1 reads done before CR reused for P/carries

    // ---- write P frags (natural dt cols of CR) ----
    #pragma unroll
    for (int mt = 0; mt < 2; mt++)
        #pragma unroll
        for (int j = 0; j < 4; j++) {
            int ra  = mw * 32 + mt * 16 + (lane >> 2);
            int col = nw * 32 + j * 8 + 2 * (lane & 3);
            *(float2*)&CR[ra * AP + col]       = make_float2(pc[mt][j][0], pc[mt][j][1]);
            *(float2*)&CR[(ra + 8) * AP + col] = make_float2(pc[mt][j][2], pc[mt][j][3]);
        }
    __syncthreads();

    // ---- parallel carry scan: 64 sequences x 64 chunks, 4 threads/sequence ----
    {
        int t = tid >> 6, seq = tid & 63;
        int bl = seq >> 5, d = seq & 31;
        float2 rl = make_float2( Inj[63 * AP + kperm(2 * d)],
                                -Inj[63 * AP + kperm(2 * d + 1)]);   // r^64
        float2 R = rl;                           // R = rl^16
        #pragma unroll
        for (int sq = 0; sq < 4; sq++) {
            float2 nR;
            nR.x = fmaf(R.x, R.x, -R.y * R.y);
            nR.y = 2.0f * R.x * R.y;
            R = nR;
        }
        float* bp = &CR[(bl * 64 + t * 16) * AP + 2 * d];
        float2 s = make_float2(0.0f, 0.0f);
        #pragma unroll
        for (int i = 0; i < 16; i++)
            s = cmad(rl, s, *(float2*)(bp + i * AP));
        Sbuf[t][seq] = s;
        __syncthreads();
        float2 X = c0S[d];
        for (int k = 0; k < t; k++)             // t uniform per warp: no divergence
            X = cmad(R, X, Sbuf[k][seq]);
        #pragma unroll
        for (int i = 0; i < 16; i++) {
            float2 p = *(float2*)(bp + i * AP);
            *(float2*)(bp + i * AP) = X;
            X = cmad(rl, X, p);
        }
    }
    __syncthreads();

    // ---- Y half1: carries x injection (K=64, dense) ----
    #pragma unroll
    for (int ks = 0; ks < 8; ks++) {
        int k0 = ks * 8;
        uint32_t a[2][4];
        ldmA(a[0], aC[0] + k0 * 4);
        ldmA(a[1], aC[1] + k0 * 4);
        #pragma unroll
        for (int j = 0; j < 4; j++) {
            float2 bv = *(float2*)&Inj[((2 * j + nw) * 8 + bn8) * AP + k0 + bCol2];
            mma8(yc[0][j], a[0], bv.x, bv.y);
            mma8(yc[1][j], a[1], bv.x, bv.y);
        }
    }

    // ---- epilogue: y = Y + D*u (exact fp32) ----
    #pragma unroll
    for (int mt = 0; mt < 2; mt++)
        #pragma unroll
        for (int half = 0; half < 2; half++) {
            int r = mw * 32 + mt * 16 + (lane >> 2) + half * 8;
            float* op = out + ((size_t)((b0 + (r >> 6)) * NH + h)) * NL + (r & 63) * 64;
            #pragma unroll
            for (int j = 0; j < 4; j++) {
                int col = (2 * j + nw) * 8 + 2 * (lane & 3);
                float2 uv = *(float2*)&Us[r * AP + col];
                float2 o2;
                o2.x = fmaf(Dv, uv.x, yc[mt][j][half * 2 + 0]);
                o2.y = fmaf(Dv, uv.y, yc[mt][j][half * 2 + 1]);
                *(float2*)(op + col) = o2;
            }
        }
}

// ---------------------------------------------------------------------------
extern "C" void kernel_launch(void* const* d_in, const int* in_sizes, int n_in,
                              void* d_out, int out_size) {
    (void)in_sizes; (void)n_in; (void)out_size;
    const float* u     = (const float*)d_in[0];
    const float* theta = (const float*)d_in[1];
    const float* a     = (const float*)d_in[2];
    const float* Dp    = (const float*)d_in[3];
    const float* b_p   = (const float*)d_in[4];
    const float* c_p   = (const float*)d_in[5];
    const float* x0    = (const float*)d_in[6];
    float* out = (float*)d_out;

    cudaFuncSetAttribute(k_fused, cudaFuncAttributeMaxDynamicSharedMemorySize, SMEMF);
    k_fused<<<1024, 256, SMEMF>>>(u, theta, a, Dp, b_p, c_p, x0, out);
}